// round 3
// baseline (speedup 1.0000x reference)
#include <cuda_runtime.h>
#include <math.h>

// ---------------------------------------------------------------------------
// Shapes: B=8192, S=8 (graph nodes), D=128, Fin=256, Mmod=8, H1=4, C1=128,
// HC1=512, OUT=256. Rows = B*S = 65536 for all big GEMMs.
// ---------------------------------------------------------------------------
#define Bsz   8192
#define Dsz   128
#define FinSz 256
#define ROWS  65536
#define HC1   512
#define OUTC  256

// Scratch (device globals; allocation is forbidden)
__device__ float g_mp[(size_t)8 * ROWS * Dsz];   // 256 MiB  [m][row][d]
__device__ float g_lv[(size_t)8 * ROWS * Dsz];   // 256 MiB
__device__ float g_h1[(size_t)ROWS * HC1];       // 128 MiB  (reused for h2)
__device__ float g_x1[(size_t)ROWS * HC1];       // 128 MiB
__device__ unsigned char g_adj[(size_t)Bsz * 64];

// ---------------------------------------------------------------------------
// 128x128 fp32 GEMM tile, BK=16, 256 threads, 8x8 microtile.
// C[r][c] = sum_k A[r][k]*W[k][c] (+ bias[c]).  All dims multiples of tiles.
// ---------------------------------------------------------------------------
template<int N, int K, bool BIAS>
__device__ __forceinline__ void gemm_tile128(
    const float* __restrict__ A, const float* __restrict__ W,
    const float* __restrict__ bias, float* __restrict__ C,
    int rowBase, int colBase)
{
    __shared__ float As[16][128];   // As[k][row]
    __shared__ float Bs[16][128];   // Bs[k][col]
    const int tid = threadIdx.x;
    const int tx = tid & 15, ty = tid >> 4;

    float acc[8][8];
#pragma unroll
    for (int i = 0; i < 8; ++i)
#pragma unroll
        for (int j = 0; j < 8; ++j) acc[i][j] = 0.f;

    for (int k0 = 0; k0 < K; k0 += 16) {
#pragma unroll
        for (int it = 0; it < 2; ++it) {            // A tile: 512 float4
            int f = it * 256 + tid;
            int row = f >> 2, c4 = f & 3;
            float4 v = *(const float4*)(A + (size_t)(rowBase + row) * K + (k0 + c4 * 4));
            As[c4 * 4 + 0][row] = v.x;
            As[c4 * 4 + 1][row] = v.y;
            As[c4 * 4 + 2][row] = v.z;
            As[c4 * 4 + 3][row] = v.w;
        }
#pragma unroll
        for (int it = 0; it < 2; ++it) {            // B tile: 512 float4
            int f = it * 256 + tid;
            int rb = f >> 5, c4 = f & 31;
            *(float4*)&Bs[rb][c4 * 4] =
                *(const float4*)(W + (size_t)(k0 + rb) * N + (colBase + c4 * 4));
        }
        __syncthreads();
#pragma unroll
        for (int kk = 0; kk < 16; ++kk) {
            float av[8], bv[8];
            *(float4*)&av[0] = *(const float4*)&As[kk][ty * 8];
            *(float4*)&av[4] = *(const float4*)&As[kk][ty * 8 + 4];
            *(float4*)&bv[0] = *(const float4*)&Bs[kk][tx * 8];
            *(float4*)&bv[4] = *(const float4*)&Bs[kk][tx * 8 + 4];
#pragma unroll
            for (int i = 0; i < 8; ++i)
#pragma unroll
                for (int j = 0; j < 8; ++j)
                    acc[i][j] = fmaf(av[i], bv[j], acc[i][j]);
        }
        __syncthreads();
    }

    float bb[8];
    if (BIAS) {
#pragma unroll
        for (int j = 0; j < 8; ++j) bb[j] = bias[colBase + tx * 8 + j];
    }
#pragma unroll
    for (int i = 0; i < 8; ++i) {
        float* Crow = C + (size_t)(rowBase + ty * 8 + i) * N + colBase + tx * 8;
        float o[8];
#pragma unroll
        for (int j = 0; j < 8; ++j) o[j] = BIAS ? acc[i][j] + bb[j] : acc[i][j];
        *(float4*)&Crow[0] = *(float4*)&o[0];
        *(float4*)&Crow[4] = *(float4*)&o[4];
    }
}

// Gauss heads: blockIdx.x selects mean/logvar, .y row tile, .z modality.
__global__ void __launch_bounds__(256) gauss_gemm_kernel(
    const float* __restrict__ priv,
    const float* __restrict__ mW, const float* __restrict__ mB,
    const float* __restrict__ lW, const float* __restrict__ lB)
{
    const int m = blockIdx.z;
    const bool isMean = (blockIdx.x == 0);
    const float* A  = priv + (size_t)m * ROWS * Dsz;
    const float* Wt = (isMean ? mW : lW) + m * Dsz * Dsz;
    const float* bt = (isMean ? mB : lB) + m * Dsz;
    float* C = (isMean ? g_mp : g_lv) + (size_t)m * ROWS * Dsz;
    gemm_tile128<Dsz, Dsz, true>(A, Wt, bt, C, blockIdx.y * 128, 0);
}

template<int N, int K>
__global__ void __launch_bounds__(256) gemm_kernel(
    const float* __restrict__ A, const float* __restrict__ W,
    float* __restrict__ C)
{
    gemm_tile128<N, K, false>(A, W, nullptr, C, blockIdx.y * 128, blockIdx.x * 128);
}

// ---------------------------------------------------------------------------
// KL + adjacency. One block per batch b, 512 threads, ~135 KB dynamic smem.
// kl[i,j,s] = 0.5*( sumlv_j - sumlv_i + sum_d ivq_j*(P_i - 2 mp_i mp_j) + T4_j - D )
// with P = exp(lv)+mp^2, ivq = exp(-lv), T4_j = sum_d mp_j^2*ivq_j.
// ---------------------------------------------------------------------------
#define ROWP 132                       // padded row stride (bank-conflict free)
#define KL_SMEM_FLOATS (4*64*ROWP + 64 + 64 + 512 + 64)

__global__ void __launch_bounds__(512) kl_adj_kernel()
{
    extern __shared__ float sm[];
    float* s_mp    = sm;
    float* s_ivq   = sm + 64 * ROWP;
    float* s_P     = sm + 2 * 64 * ROWP;
    float* s_lv    = sm + 3 * 64 * ROWP;
    float* s_sumlv = sm + 4 * 64 * ROWP;
    float* s_T4    = s_sumlv + 64;
    float* s_kl    = s_T4 + 64;        // [64 pairs][8 s]
    float* s_km    = s_kl + 512;

    const int tid = threadIdx.x;
    const int b = blockIdx.x;

    // Phase A: load mp/lv (64 rows x 128 d), transform, store padded.
#pragma unroll
    for (int it = 0; it < 4; ++it) {
        int f = it * 512 + tid;          // float4 id, 2048 total
        int row = f >> 5;                // 0..63  (m*8+s)
        int d   = (f & 31) * 4;
        int m = row >> 3, s = row & 7;
        size_t gbase = ((size_t)m * ROWS + (size_t)b * 8 + s) * Dsz + d;
        float4 mpv = *(const float4*)(g_mp + gbase);
        float4 lvv = *(const float4*)(g_lv + gbase);
        float4 iv, Pv;
        iv.x = __expf(-lvv.x); iv.y = __expf(-lvv.y);
        iv.z = __expf(-lvv.z); iv.w = __expf(-lvv.w);
        Pv.x = __expf(lvv.x) + mpv.x * mpv.x;
        Pv.y = __expf(lvv.y) + mpv.y * mpv.y;
        Pv.z = __expf(lvv.z) + mpv.z * mpv.z;
        Pv.w = __expf(lvv.w) + mpv.w * mpv.w;
        int so = row * ROWP + d;
        *(float4*)(s_mp  + so) = mpv;
        *(float4*)(s_ivq + so) = iv;
        *(float4*)(s_P   + so) = Pv;
        *(float4*)(s_lv  + so) = lvv;
    }
    __syncthreads();

    // Phase B: per-row sumlv and T4 (16 warps x 4 rows).
    {
        int w = tid >> 5, lane = tid & 31;
#pragma unroll
        for (int rr = 0; rr < 4; ++rr) {
            int r = w * 4 + rr;
            float slv = 0.f, t4 = 0.f;
#pragma unroll
            for (int k = 0; k < 4; ++k) {
                int d = lane + 32 * k;
                float lv = s_lv[r * ROWP + d];
                float mp = s_mp[r * ROWP + d];
                float iq = s_ivq[r * ROWP + d];
                slv += lv;
                t4  += mp * mp * iq;
            }
#pragma unroll
            for (int off = 16; off > 0; off >>= 1) {
                slv += __shfl_down_sync(0xffffffffu, slv, off);
                t4  += __shfl_down_sync(0xffffffffu, t4, off);
            }
            if (lane == 0) { s_sumlv[r] = slv; s_T4[r] = t4; }
        }
    }
    __syncthreads();

    // Phase C: one thread per (pair p, s). p=(i,j).
    {
        int p = tid >> 3, s = tid & 7;
        int i = p >> 3, j = p & 7;
        int ri = i * 8 + s, rj = j * 8 + s;
        const float4* Pi = (const float4*)(s_P   + ri * ROWP);
        const float4* Mi = (const float4*)(s_mp  + ri * ROWP);
        const float4* Qj = (const float4*)(s_ivq + rj * ROWP);
        const float4* Mj = (const float4*)(s_mp  + rj * ROWP);
        float acc = 0.f;
#pragma unroll
        for (int q = 0; q < 32; ++q) {
            float4 pi = Pi[q], mi = Mi[q], qj = Qj[q], mj = Mj[q];
            acc += qj.x * (pi.x - 2.f * mi.x * mj.x);
            acc += qj.y * (pi.y - 2.f * mi.y * mj.y);
            acc += qj.z * (pi.z - 2.f * mi.z * mj.z);
            acc += qj.w * (pi.w - 2.f * mi.w * mj.w);
        }
        s_kl[tid] = 0.5f * (s_sumlv[rj] - s_sumlv[ri] + acc + s_T4[rj] - 128.f);
    }
    __syncthreads();

    if (tid < 64) {
        float km = 0.f;
#pragma unroll
        for (int k = 0; k < 8; ++k) km += s_kl[tid * 8 + k];
        s_km[tid] = km * 0.125f;
    }
    __syncthreads();

    if (tid < 64) {
        int i = tid >> 3, j = tid & 7;
        bool a;
        if (i == j)      a = true;
        else if (i < j)  a = (s_km[tid] > 0.5f);
        else             a = (s_km[j * 8 + i] > 0.5f);
        g_adj[(size_t)b * 64 + tid] = a ? 1 : 0;
    }
}

// ---------------------------------------------------------------------------
// GAT attention over 8 nodes per batch. One block per b, 256 threads.
// Hin: [ROWS, HH*CC] bias-free features. Out = softmax-agg + bias (+relu).
// ---------------------------------------------------------------------------
template<int HH, int CC, bool RELU>
__global__ void __launch_bounds__(256) gat_attn_kernel(
    const float* __restrict__ Hin,
    const float* __restrict__ a_src, const float* __restrict__ a_dst,
    const float* __restrict__ bias, float* __restrict__ Out)
{
    constexpr int HC = HH * CC;
    constexpr int NDOT = 2 * 8 * HH;        // src + dst dots
    constexpr int TPD = 256 / NDOT;         // threads per dot
    __shared__ float s_h[8 * HC];
    __shared__ float s_att[NDOT];
    __shared__ float s_alpha[8 * HH * 8];   // [(i*HH+h)][j]

    const int tid = threadIdx.x;
    const int b = blockIdx.x;

    // Load h tile (8 x HC) float4
#pragma unroll
    for (int it = 0; it < (8 * HC) / (4 * 256); ++it) {
        int f = it * 256 + tid;
        *(float4*)&s_h[f * 4] =
            *(const float4*)(Hin + (size_t)b * 8 * HC + f * 4);
    }
    __syncthreads();

    // Dots: asrc/adst per (node m, head h)
    {
        int dot = tid / TPD, g = tid % TPD;
        int isd = dot >= 8 * HH;
        int rem = dot - (isd ? 8 * HH : 0);
        int m = rem / HH, h = rem % HH;
        const float* av = (isd ? a_dst : a_src) + h * CC;
        float acc = 0.f;
#pragma unroll
        for (int k = 0; k < CC / TPD; ++k) {
            int c = g + TPD * k;
            acc += s_h[m * HC + h * CC + c] * av[c];
        }
#pragma unroll
        for (int off = TPD / 2; off > 0; off >>= 1)
            acc += __shfl_down_sync(0xffffffffu, acc, off, TPD);
        if (g == 0) s_att[dot] = acc;
    }
    __syncthreads();

    // Softmax over sources j for each (target i, head h)
    if (tid < 8 * HH) {
        int i = tid / HH, h = tid % HH;
        float adi = s_att[8 * HH + i * HH + h];
        float lg[8];
        float mx = -1e30f;
#pragma unroll
        for (int j = 0; j < 8; ++j) {
            float e = adi + s_att[j * HH + h];
            e = (e > 0.f) ? e : 0.2f * e;                 // leaky_relu 0.2
            if (!g_adj[(size_t)b * 64 + i * 8 + j]) e = -1e9f;
            lg[j] = e;
            mx = fmaxf(mx, e);
        }
        float ssum = 0.f;
#pragma unroll
        for (int j = 0; j < 8; ++j) { lg[j] = __expf(lg[j] - mx); ssum += lg[j]; }
        float inv = 1.f / ssum;
#pragma unroll
        for (int j = 0; j < 8; ++j) s_alpha[tid * 8 + j] = lg[j] * inv;
    }
    __syncthreads();

    // Aggregate + bias (+relu)
#pragma unroll
    for (int it = 0; it < (8 * HC) / 256; ++it) {
        int o = it * 256 + tid;
        int i = o / HC, hc = o % HC, h = hc / CC;
        float acc = 0.f;
#pragma unroll
        for (int j = 0; j < 8; ++j)
            acc += s_alpha[(i * HH + h) * 8 + j] * s_h[j * HC + hc];
        acc += bias[hc];
        if (RELU) acc = fmaxf(acc, 0.f);
        Out[(size_t)b * 8 * HC + o] = acc;
    }
}

// ---------------------------------------------------------------------------
extern "C" void kernel_launch(void* const* d_in, const int* in_sizes, int n_in,
                              void* d_out, int out_size)
{
    const float* distilled = (const float*)d_in[0];
    const float* priv      = (const float*)d_in[1];
    const float* gmW  = (const float*)d_in[2];
    const float* gmB  = (const float*)d_in[3];
    const float* glW  = (const float*)d_in[4];
    const float* glB  = (const float*)d_in[5];
    const float* g1W  = (const float*)d_in[6];
    const float* g1as = (const float*)d_in[7];
    const float* g1ad = (const float*)d_in[8];
    const float* g1b  = (const float*)d_in[9];
    const float* g2W  = (const float*)d_in[10];
    const float* g2as = (const float*)d_in[11];
    const float* g2ad = (const float*)d_in[12];
    const float* g2b  = (const float*)d_in[13];
    float* out = (float*)d_out;

    void *p_h1 = nullptr, *p_x1 = nullptr;
    cudaGetSymbolAddress(&p_h1, g_h1);
    cudaGetSymbolAddress(&p_x1, g_x1);
    float* h1 = (float*)p_h1;
    float* x1 = (float*)p_x1;

    static bool attr_done = false;
    cudaFuncSetAttribute(kl_adj_kernel,
                         cudaFuncAttributeMaxDynamicSharedMemorySize,
                         KL_SMEM_FLOATS * (int)sizeof(float));
    (void)attr_done;

    // 1. Gaussian heads (mean + logvar, 8 modalities)
    gauss_gemm_kernel<<<dim3(2, ROWS / 128, 8), 256>>>(priv, gmW, gmB, glW, glB);

    // 2. KL -> adjacency
    kl_adj_kernel<<<Bsz, 512, KL_SMEM_FLOATS * (int)sizeof(float)>>>();

    // 3. GAT1: h1 = distilled @ W1 ; attention ; relu -> x1
    gemm_kernel<HC1, FinSz><<<dim3(HC1 / 128, ROWS / 128), 256>>>(distilled, g1W, h1);
    gat_attn_kernel<4, 128, true><<<Bsz, 256>>>(h1, g1as, g1ad, g1b, x1);

    // 4. GAT2: h2 = x1 @ W2 (reuse h1 buffer) ; attention -> out
    gemm_kernel<OUTC, HC1><<<dim3(OUTC / 128, ROWS / 128), 256>>>(x1, g2W, h1);
    gat_attn_kernel<1, 256, false><<<Bsz, 256>>>(h1, g2as, g2ad, g2b, out);
}